// round 12
// baseline (speedup 1.0000x reference)
#include <cuda_runtime.h>
#include <cstdint>

// out[r][c] = in[2r+1][2c+1], in: 8192x8192 f32, out: 4096x4096 f32.
//
// DRAM-bound at the ~6 TB/s mixed read+write HBM ceiling. R11 established
// the steady-state winner: 2 output rows per thread, default load AND
// store policy (31.26 us). This round keeps that structure but widens all
// accesses to 256-bit (sm_103a v8.b32): each thread handles 2 rows x 8
// output cols via 4x ld.global.v8 -> 2x st.global.v8, all default policy.
// Warp requests are 1024B contiguous; instruction count halves.

static constexpr int N_IN  = 8192;
static constexpr int N_OUT = 4096;

struct v8 { uint32_t r[8]; };

__device__ __forceinline__ v8 ld256(const float* p) {
    v8 v;
    asm("ld.global.v8.b32 {%0,%1,%2,%3,%4,%5,%6,%7}, [%8];"
        : "=r"(v.r[0]), "=r"(v.r[1]), "=r"(v.r[2]), "=r"(v.r[3]),
          "=r"(v.r[4]), "=r"(v.r[5]), "=r"(v.r[6]), "=r"(v.r[7])
        : "l"(p));
    return v;
}

__device__ __forceinline__ void st256(float* p, uint32_t a, uint32_t b,
                                      uint32_t c, uint32_t d, uint32_t e,
                                      uint32_t f, uint32_t g, uint32_t h) {
    asm volatile("st.global.v8.b32 [%0], {%1,%2,%3,%4,%5,%6,%7,%8};"
                 :: "l"(p), "r"(a), "r"(b), "r"(c), "r"(d),
                    "r"(e), "r"(f), "r"(g), "r"(h)
                 : "memory");
}

__global__ void __launch_bounds__(256)
downsample2x_kernel(const float* __restrict__ in, float* __restrict__ out) {
    unsigned tid = blockIdx.x * blockDim.x + threadIdx.x;  // 0 .. 1,048,575
    unsigned v   = tid & 511;          // output cols 8v..8v+7
    unsigned rg  = tid >> 9;           // row group 0..2047: output rows 2rg, 2rg+1

    // Input rows 4rg+1 and 4rg+3; input cols 16v..16v+15 (64 bytes).
    const float* p0 = in + (size_t)(4u * rg + 1u) * N_IN + 16u * v;
    const float* p1 = p0 + 2u * N_IN;

    // Front-batched default-policy 256-bit loads (MLP_p1 = 4).
    v8 a0 = ld256(p0);
    v8 b0 = ld256(p0 + 8);
    v8 a1 = ld256(p1);
    v8 b1 = ld256(p1 + 8);

    float* q0 = out + (size_t)(2u * rg) * N_OUT + 8u * v;
    float* q1 = q0 + N_OUT;

    // Odd elements: indices 1,3,5,7 of each v8. Default-policy stores.
    st256(q0, a0.r[1], a0.r[3], a0.r[5], a0.r[7],
              b0.r[1], b0.r[3], b0.r[5], b0.r[7]);
    st256(q1, a1.r[1], a1.r[3], a1.r[5], a1.r[7],
              b1.r[1], b1.r[3], b1.r[5], b1.r[7]);
}

extern "C" void kernel_launch(void* const* d_in, const int* in_sizes, int n_in,
                              void* d_out, int out_size) {
    const float* in  = (const float*)d_in[0];
    float*       out = (float*)d_out;

    const int total_threads = 2048 * 512;     // 1,048,576
    const int block = 256;
    const int grid  = total_threads / block;  // 4096

    downsample2x_kernel<<<grid, block>>>(in, out);
}